// round 12
// baseline (speedup 1.0000x reference)
#include <cuda_runtime.h>
#include <cuda_fp16.h>
#include <math.h>
#include <stdint.h>

// ---------------- scratch ----------------
#define NBUF (2*384*1024)
__device__ float g_q [NBUF];
__device__ float g_xs[NBUF];
__device__ float g_k [NBUF];
__device__ float g_v [NBUF];
__device__ float g_o [NBUF];
__device__ float2 g_pos[12*1024];

#define SCALE 0.17677669529663687f

typedef unsigned long long u64;
__device__ __forceinline__ uint32_t f2tf(float f) {
    uint32_t u; asm("cvt.rna.tf32.f32 %0, %1;" : "=r"(u) : "f"(f)); return u;
}
__device__ __forceinline__ void mma_tf32(float* d, const uint32_t* a, const uint32_t* b) {
    asm volatile("mma.sync.aligned.m16n8k8.row.col.f32.tf32.tf32.f32 "
        "{%0,%1,%2,%3}, {%4,%5,%6,%7}, {%8,%9}, {%0,%1,%2,%3};"
        : "+f"(d[0]), "+f"(d[1]), "+f"(d[2]), "+f"(d[3])
        : "r"(a[0]), "r"(a[1]), "r"(a[2]), "r"(a[3]), "r"(b[0]), "r"(b[1]));
}
// packed fp32x2 fma (sm_100+ PTX, base-arch feature)
__device__ __forceinline__ u64 pack2(float x) {
    u64 d; asm("mov.b64 %0, {%1, %1};" : "=l"(d) : "f"(x)); return d;
}
__device__ __forceinline__ void fma2(u64& d, u64 a, u64 b) {
    asm("fma.rn.f32x2 %0, %1, %2, %0;" : "+l"(d) : "l"(a), "l"(b));
}
// fp16x2 bit casts
__device__ __forceinline__ uint32_t h2_to_u32(__half2 h) {
    union { __half2 h; uint32_t u; } c; c.h = h; return c.u;
}
__device__ __forceinline__ __half2 u32_to_h2(uint32_t u) {
    union { uint32_t u; __half2 h; } c; c.u = u; return c.h;
}

// =======================================================================
// Channel-major tf32 mma GEMM (round 8, unchanged)
// =======================================================================
#define AS_STRIDE 36
#define BS_STRIDE 136
__device__ void gemm_body(
    const float* __restrict__ W, const float* __restrict__ bias,
    const float* __restrict__ X, float* __restrict__ Y,
    int m0, int n0)
{
    extern __shared__ float dsm[];
    float* Asm = dsm;                    // [2][64*36]
    float* Bsm = dsm + 2*64*AS_STRIDE;   // [2][32*136]

    int tid = threadIdx.x, lane = tid & 31, wid = tid >> 5;
    int wm = wid & 1, wn = wid >> 1;
    int g = lane >> 2, c = lane & 3;

    int ar = tid >> 2, aq = (tid & 3) * 8;
    int kb = tid >> 3, nq = (tid & 7) * 16;
    const float* Wp = W + (size_t)(m0 + ar) * 384 + aq;
    const float* Xp = X + (size_t)kb * 1024 + n0 + nq;

    float4 pa[2], pb[4];
    #pragma unroll
    for (int i = 0; i < 2; i++) pa[i] = *(const float4*)(Wp + i*4);
    #pragma unroll
    for (int i = 0; i < 4; i++) pb[i] = *(const float4*)(Xp + i*4);

    float acc[2][4][4];
    #pragma unroll
    for (int mt = 0; mt < 2; mt++)
        #pragma unroll
        for (int nt = 0; nt < 4; nt++)
            #pragma unroll
            for (int i = 0; i < 4; i++) acc[mt][nt][i] = 0.f;

    int buf = 0;
    #pragma unroll 1
    for (int ch = 0; ch < 12; ch++) {
        float* Asb = Asm + buf * 64 * AS_STRIDE;
        float* Bsb = Bsm + buf * 32 * BS_STRIDE;
        #pragma unroll
        for (int i = 0; i < 2; i++) {
            uint4 t = make_uint4(f2tf(pa[i].x), f2tf(pa[i].y), f2tf(pa[i].z), f2tf(pa[i].w));
            *(uint4*)&Asb[ar*AS_STRIDE + aq + i*4] = t;
        }
        #pragma unroll
        for (int i = 0; i < 4; i++) {
            uint4 t = make_uint4(f2tf(pb[i].x), f2tf(pb[i].y), f2tf(pb[i].z), f2tf(pb[i].w));
            *(uint4*)&Bsb[kb*BS_STRIDE + nq + i*4] = t;
        }
        __syncthreads();
        if (ch < 11) {
            #pragma unroll
            for (int i = 0; i < 2; i++) pa[i] = *(const float4*)(Wp + (ch+1)*32 + i*4);
            #pragma unroll
            for (int i = 0; i < 4; i++) pb[i] = *(const float4*)(Xp + (size_t)(ch+1)*32*1024 + i*4);
        }
        const uint32_t* Au = (const uint32_t*)Asb;
        const uint32_t* Bu = (const uint32_t*)Bsb;
        #pragma unroll
        for (int kk = 0; kk < 4; kk++) {
            uint32_t afr[2][4];
            #pragma unroll
            for (int mt = 0; mt < 2; mt++) {
                int rb = wm*32 + mt*16;
                afr[mt][0] = Au[(rb + g    )*AS_STRIDE + kk*8 + c];
                afr[mt][1] = Au[(rb + g + 8)*AS_STRIDE + kk*8 + c];
                afr[mt][2] = Au[(rb + g    )*AS_STRIDE + kk*8 + c + 4];
                afr[mt][3] = Au[(rb + g + 8)*AS_STRIDE + kk*8 + c + 4];
            }
            #pragma unroll
            for (int nt = 0; nt < 4; nt++) {
                int nb = wn*32 + nt*8;
                uint32_t bfr[2];
                bfr[0] = Bu[(kk*8 + c    )*BS_STRIDE + nb + g];
                bfr[1] = Bu[(kk*8 + c + 4)*BS_STRIDE + nb + g];
                mma_tf32(acc[0][nt], afr[0], bfr);
                mma_tf32(acc[1][nt], afr[1], bfr);
            }
        }
        buf ^= 1;
    }

    int c2 = (lane & 3) * 2;
    #pragma unroll
    for (int mt = 0; mt < 2; mt++) {
        int row = m0 + wm*32 + mt*16 + g;
        float b0 = bias[row], b1 = bias[row + 8];
        #pragma unroll
        for (int nt = 0; nt < 4; nt++) {
            int col = n0 + wn*32 + nt*8 + c2;
            *(float2*)&Y[(size_t)row*1024 + col] =
                make_float2(acc[mt][nt][0] + b0, acc[mt][nt][1] + b0);
            *(float2*)&Y[(size_t)(row + 8)*1024 + col] =
                make_float2(acc[mt][nt][2] + b1, acc[mt][nt][3] + b1);
        }
    }
}

__global__ __launch_bounds__(256) void gemm_mma(
    const float* __restrict__ W, const float* __restrict__ bias,
    const float* __restrict__ X, float* __restrict__ Y)
{
    int b = blockIdx.z;
    gemm_body(W, bias, X + (size_t)b*393216, Y + (size_t)b*393216,
              blockIdx.y*64, blockIdx.x*128);
}

__global__ __launch_bounds__(256) void gemm_mma_kv(
    const float* __restrict__ Wk, const float* __restrict__ bk,
    const float* __restrict__ Wv, const float* __restrict__ bv,
    const float* __restrict__ X, float* __restrict__ Yk, float* __restrict__ Yv)
{
    int b = blockIdx.z;
    int sel = blockIdx.y >= 6;
    int m0 = (blockIdx.y - sel*6) * 64;
    gemm_body(sel ? Wv : Wk, sel ? bv : bk, X + (size_t)b*393216,
              (sel ? Yv : Yk) + (size_t)b*393216, m0, blockIdx.x*128);
}

// =======================================================================
// depthwise 7x7 conv (round 2/8, unchanged)
// =======================================================================
__global__ __launch_bounds__(256) void dwconv_kernel(
    const float* __restrict__ q, const float* __restrict__ dw_w,
    const float* __restrict__ dw_b, float* __restrict__ tmp)
{
    int plane = blockIdx.x;
    int ch = plane & 63;
    __shared__ float s[1024];
    __shared__ float w[49];
    const float* qp = q + (size_t)plane * 1024;
    int tid = threadIdx.x;
    *(float4*)&s[tid*4] = *(const float4*)(qp + tid*4);
    if (tid < 49) w[tid] = dw_w[ch*49 + tid];
    float bch = dw_b[ch];
    __syncthreads();
    #pragma unroll
    for (int pp = 0; pp < 4; pp++) {
        int pix = tid + pp*256;
        int py = pix >> 5, px = pix & 31;
        float a = bch;
        #pragma unroll
        for (int ky = 0; ky < 7; ky++) {
            int iy = py + ky - 3;
            if (iy < 0 || iy > 31) continue;
            #pragma unroll
            for (int kx = 0; kx < 7; kx++) {
                int ix = px + kx - 3;
                if (ix < 0 || ix > 31) continue;
                a += w[ky*7+kx] * s[iy*32+ix];
            }
        }
        tmp[(size_t)plane*1024 + pix] = a;
    }
}

// =======================================================================
// LN + GELU + 1x1 + tanh -> pos (round 2/8, unchanged)
// =======================================================================
__global__ __launch_bounds__(256) void offs_kernel(
    const float* __restrict__ tmp, const float* __restrict__ ln_g,
    const float* __restrict__ ln_b, const float* __restrict__ pw_w,
    float2* __restrict__ pos)
{
    int bg = blockIdx.x >> 3;
    int p0 = (blockIdx.x & 7) * 128;
    int tid = threadIdx.x;
    int pl = tid & 127, half = tid >> 7;
    int pix = p0 + pl;
    const float* tp = tmp + (size_t)bg*65536 + (size_t)half*32768 + pix;

    __shared__ float red[256], red2[256], mu_s[128], rs_s[128];

    float vals[32];
    float s1 = 0.f;
    #pragma unroll
    for (int i = 0; i < 32; i++) { vals[i] = tp[i*1024]; s1 += vals[i]; }
    red[tid] = s1;
    __syncthreads();
    if (half == 0) mu_s[pl] = (red[pl] + red[pl+128]) * (1.f/64.f);
    __syncthreads();
    float mu = mu_s[pl];
    float s2 = 0.f;
    #pragma unroll
    for (int i = 0; i < 32; i++) { float d = vals[i]-mu; s2 += d*d; }
    red[tid] = s2;
    __syncthreads();
    if (half == 0) rs_s[pl] = rsqrtf((red[pl]+red[pl+128])*(1.f/64.f) + 1e-5f);
    __syncthreads();
    float rs = rs_s[pl];
    float sy = 0.f, sx = 0.f;
    #pragma unroll
    for (int i = 0; i < 32; i++) {
        int cch = half*32 + i;
        float o = (vals[i]-mu)*rs*ln_g[cch] + ln_b[cch];
        o = 0.5f*o*(1.f + erff(o*0.70710678118654752f));
        sy += o * pw_w[cch];
        sx += o * pw_w[64+cch];
    }
    red[tid] = sy; red2[tid] = sx;
    __syncthreads();
    if (half == 0) {
        float oy = tanhf(red[pl]+red[pl+128]) * 0.0625f;
        float ox = tanhf(red2[pl]+red2[pl+128]) * 0.0625f;
        int py = pix >> 5, px = pix & 31;
        float refy = ((py + 0.5f)*(1.f/16.f)) - 1.f;
        float refx = ((px + 0.5f)*(1.f/16.f)) - 1.f;
        pos[bg*1024 + pix] = make_float2(ox + refx, oy + refy);
    }
}

// =======================================================================
// grid sample (round 2/8, unchanged)
// =======================================================================
__global__ __launch_bounds__(256) void sample_kernel(
    const float* __restrict__ x, const float2* __restrict__ pos,
    float* __restrict__ xs)
{
    int idx = blockIdx.x * 256 + threadIdx.x;
    int s  = idx & 1023;
    int bg = idx >> 16;
    float2 p = pos[bg * 1024 + s];
    float gx = (p.x + 1.f) * 0.5f * 31.f;
    float gy = (p.y + 1.f) * 0.5f * 31.f;
    float x0f = floorf(gx), y0f = floorf(gy);
    float wx = gx - x0f, wy = gy - y0f;
    int x0 = (int)x0f, y0 = (int)y0f;
    const float* xp = x + (size_t)(idx >> 10) * 1024;
    float r = 0.f;
    bool vx0 = (x0 >= 0) & (x0 <= 31), vx1 = (x0 >= -1) & (x0 <= 30);
    bool vy0 = (y0 >= 0) & (y0 <= 31), vy1 = (y0 >= -1) & (y0 <= 30);
    if (vx0 && vy0) r += (1.f - wx) * (1.f - wy) * xp[y0 * 32 + x0];
    if (vx1 && vy0) r += wx * (1.f - wy) * xp[y0 * 32 + x0 + 1];
    if (vx0 && vy1) r += (1.f - wx) * wy * xp[(y0 + 1) * 32 + x0];
    if (vx1 && vy1) r += wx * wy * xp[(y0 + 1) * 32 + x0 + 1];
    xs[idx] = r;
}

// =======================================================================
// fused attention: round-10 structure, P in fp16 smem (3 CTAs/SM),
// PV v-chunk register prefetch restored.
// smem floats: p_h[1024*20 half = 10240 f] | v[4608] | q[512] | redw[128] | fin[32]
// =======================================================================
#define P_STRIDE 20
#define V_STRIDE 36
#define ACC(r, j) (((float*)accp)[(((r) >> 1)*4 + (j))*2 + ((r) & 1)])
__global__ __launch_bounds__(256, 3) void attn_kernel(
    const float* __restrict__ qg, const float* __restrict__ kg,
    const float* __restrict__ vg, const float2* __restrict__ pos,
    const float* __restrict__ rpe, float* __restrict__ out)
{
    extern __shared__ float sm[];
    __half* p_h = (__half*)sm;              // 1024*20 halves = 40960 B
    float* v_s  = sm + 10240;               // 4608 floats
    float* q_s  = sm + 10240 + 4608;        // 512  [c*16 + r]
    float* redw = q_s + 512;                // 128  [r*8 + warp]
    float* fin  = redw + 128;               // 32

    int bh = blockIdx.y;
    int m0 = blockIdx.x * 16;
    int head = bh % 12;
    int bg = (bh / 12) * 6 + (head >> 1);
    int tid = threadIdx.x;
    int lane = tid & 31, warp = tid >> 5;

    #pragma unroll
    for (int i = tid; i < 512; i += 256) {
        int c = i >> 4, r = i & 15;
        q_s[i] = qg[(size_t)(bh*32 + c)*1024 + m0 + r] * SCALE;
    }
    __syncthreads();

    // ---- scores (f32x2: rows paired, k broadcast packed)
    u64 accp[8][4];
    #pragma unroll
    for (int p = 0; p < 8; p++)
        #pragma unroll
        for (int j = 0; j < 4; j++) accp[p][j] = 0ull;

    const float* kb = kg + (size_t)bh * 32768;
    #pragma unroll 4
    for (int c = 0; c < 32; c++) {
        u64 K0 = pack2(kb[c*1024 + tid]);
        u64 K1 = pack2(kb[c*1024 + tid + 256]);
        u64 K2 = pack2(kb[c*1024 + tid + 512]);
        u64 K3 = pack2(kb[c*1024 + tid + 768]);
        #pragma unroll
        for (int p = 0; p < 8; p++) {
            u64 qp = *(const u64*)&q_s[c*16 + p*2];
            fma2(accp[p][0], qp, K0);
            fma2(accp[p][1], qp, K1);
            fma2(accp[p][2], qp, K2);
            fma2(accp[p][3], qp, K3);
        }
    }

    { // RPE bilinear bias (y constant over the 16 rows of this block)
        const float* T = rpe + head * 3969;
        int yq = m0 >> 5, xb = m0 & 31;
        float qy  = (yq + 0.5f) * (1.f/16.f) - 1.f;
        float qx0 = (xb + 0.5f) * (1.f/16.f) - 1.f;
        #pragma unroll
        for (int j = 0; j < 4; j++) {
            float2 p = pos[bg*1024 + tid + 256*j];
            float gy = fmaf(qy - p.y, 15.5f, 31.f);
            float y0f = floorf(gy);
            float wy = gy - y0f;
            int y0 = (int)y0f;
            float vy0 = (y0 >= 0 && y0 <= 62) ? 1.f : 0.f;
            float vy1 = (y0 >= -1 && y0 <= 61) ? 1.f : 0.f;
            int yc0 = min(max(y0, 0), 62);
            int yc1 = min(max(y0 + 1, 0), 62);
            const float* T0 = T + yc0*63;
            const float* T1 = T + yc1*63;
            float w0y = (1.f - wy) * vy0;
            float w1y = wy * vy1;
            float Cx = fmaf(qx0 - p.x, 15.5f, 31.f);
            #pragma unroll
            for (int r = 0; r < 16; r++) {
                float gx = fmaf((float)r, 0.96875f, Cx);
                float x0f = floorf(gx);
                float wx = gx - x0f;
                int x0 = (int)x0f;
                float vx0 = (x0 >= 0 && x0 <= 62) ? 1.f : 0.f;
                float vx1 = (x0 >= -1 && x0 <= 61) ? 1.f : 0.f;
                int xc0 = min(max(x0, 0), 62);
                int xc1 = min(max(x0 + 1, 0), 62);
                float t00 = T0[xc0], t01 = T0[xc1];
                float t10 = T1[xc0], t11 = T1[xc1];
                float wx0 = (1.f - wx) * vx0, wx1 = wx * vx1;
                ACC(r, j) += w0y * (wx0*t00 + wx1*t01) + w1y * (wx0*t10 + wx1*t11);
            }
        }
    }

    // softmax
    float rv[16];
    #pragma unroll
    for (int r = 0; r < 16; r++)
        rv[r] = fmaxf(fmaxf(ACC(r,0), ACC(r,1)), fmaxf(ACC(r,2), ACC(r,3)));
    #pragma unroll
    for (int off = 16; off >= 1; off >>= 1)
        #pragma unroll
        for (int r = 0; r < 16; r++)
            rv[r] = fmaxf(rv[r], __shfl_xor_sync(0xffffffffu, rv[r], off));
    if (lane == 0)
        #pragma unroll
        for (int r = 0; r < 16; r++) redw[r*8 + warp] = rv[r];
    __syncthreads();
    if (tid < 16) {
        float m = redw[tid*8];
        #pragma unroll
        for (int w = 1; w < 8; w++) m = fmaxf(m, redw[tid*8 + w]);
        fin[tid] = m;
    }
    __syncthreads();
    #pragma unroll
    for (int r = 0; r < 16; r++) {
        float m = fin[r];
        float s = 0.f;
        #pragma unroll
        for (int j = 0; j < 4; j++) { ACC(r,j) = __expf(ACC(r,j) - m); s += ACC(r,j); }
        rv[r] = s;
    }
    #pragma unroll
    for (int off = 16; off >= 1; off >>= 1)
        #pragma unroll
        for (int r = 0; r < 16; r++)
            rv[r] += __shfl_xor_sync(0xffffffffu, rv[r], off);
    if (lane == 0)
        #pragma unroll
        for (int r = 0; r < 16; r++) redw[r*8 + warp] = rv[r];
    __syncthreads();
    if (tid < 16) {
        float s = 0.f;
        #pragma unroll
        for (int w = 0; w < 8; w++) s += redw[tid*8 + w];
        fin[16 + tid] = 1.f / s;
    }

    // store exp'd p transposed as fp16: p_h[n*20 + r]
    #pragma unroll
    for (int j = 0; j < 4; j++) {
        int n = tid + 256*j;
        #pragma unroll
        for (int rq = 0; rq < 4; rq++) {
            __half2 h0 = __floats2half2_rn(ACC(rq*4+0, j), ACC(rq*4+1, j));
            __half2 h1 = __floats2half2_rn(ACC(rq*4+2, j), ACC(rq*4+3, j));
            uint2 pk;
            pk.x = h2_to_u32(h0);
            pk.y = h2_to_u32(h1);
            *(uint2*)&p_h[n*P_STRIDE + rq*4] = pk;
        }
    }
    __syncthreads();

    // PV (f32x2, v-chunk register prefetch)
    int combo = tid >> 3;
    int split = tid & 7;
    int cq = (combo & 7) * 4;
    int rq = (combo >> 3) * 4;
    u64 o2[4][2];
    #pragma unroll
    for (int ri = 0; ri < 4; ri++) { o2[ri][0] = 0ull; o2[ri][1] = 0ull; }
    const float* vb = vg + (size_t)bh * 32768;

    int lc = tid & 31;
    int nb = (tid >> 5) * 16;
    float4 vp[4];
    #pragma unroll
    for (int i = 0; i < 4; i++)
        vp[i] = *(const float4*)(vb + lc*1024 + nb + i*4);

    #pragma unroll 1
    for (int chk = 0; chk < 8; chk++) {
        #pragma unroll
        for (int i = 0; i < 4; i++) {
            v_s[(nb+i*4+0)*V_STRIDE + lc] = vp[i].x;
            v_s[(nb+i*4+1)*V_STRIDE + lc] = vp[i].y;
            v_s[(nb+i*4+2)*V_STRIDE + lc] = vp[i].z;
            v_s[(nb+i*4+3)*V_STRIDE + lc] = vp[i].w;
        }
        __syncthreads();
        if (chk < 7) {
            #pragma unroll
            for (int i = 0; i < 4; i++)
                vp[i] = *(const float4*)(vb + lc*1024 + (chk+1)*128 + nb + i*4);
        }
        #pragma unroll
        for (int i = 0; i < 16; i++) {
            int nl = i*8 + split;
            uint2 ph = *(const uint2*)&p_h[(chk*128 + nl)*P_STRIDE + rq];
            float2 f01 = __half22float2(u32_to_h2(ph.x));
            float2 f23 = __half22float2(u32_to_h2(ph.y));
            ulonglong2 vv = *(const ulonglong2*)&v_s[nl*V_STRIDE + cq];
            u64 P0 = pack2(f01.x), P1 = pack2(f01.y), P2 = pack2(f23.x), P3 = pack2(f23.y);
            fma2(o2[0][0], P0, vv.x); fma2(o2[0][1], P0, vv.y);
            fma2(o2[1][0], P1, vv.x); fma2(o2[1][1], P1, vv.y);
            fma2(o2[2][0], P2, vv.x); fma2(o2[2][1], P2, vv.y);
            fma2(o2[3][0], P3, vv.x); fma2(o2[3][1], P3, vv.y);
        }
        __syncthreads();
    }
    float o4[4][4];
    #pragma unroll
    for (int ri = 0; ri < 4; ri++) {
        float2 a = *(float2*)&o2[ri][0];
        float2 b = *(float2*)&o2[ri][1];
        o4[ri][0] = a.x; o4[ri][1] = a.y; o4[ri][2] = b.x; o4[ri][3] = b.y;
    }
    #pragma unroll
    for (int off = 4; off >= 1; off >>= 1)
        #pragma unroll
        for (int ri = 0; ri < 4; ri++)
            #pragma unroll
            for (int ci = 0; ci < 4; ci++)
                o4[ri][ci] += __shfl_xor_sync(0xffffffffu, o4[ri][ci], off);
    if (split == 0) {
        #pragma unroll
        for (int ri = 0; ri < 4; ri++) {
            float inv = fin[16 + rq + ri];
            #pragma unroll
            for (int ci = 0; ci < 4; ci++)
                out[(size_t)(bh*32 + cq + ci)*1024 + m0 + rq + ri] = o4[ri][ci] * inv;
        }
    }
}

// ---------------- launch ----------------
extern "C" void kernel_launch(void* const* d_in, const int* in_sizes, int n_in,
                              void* d_out, int out_size)
{
    const float* x    = (const float*)d_in[0];
    const float* Wq   = (const float*)d_in[1];
    const float* bq   = (const float*)d_in[2];
    const float* Wk   = (const float*)d_in[3];
    const float* bk   = (const float*)d_in[4];
    const float* Wv   = (const float*)d_in[5];
    const float* bv   = (const float*)d_in[6];
    const float* Wo   = (const float*)d_in[7];
    const float* bo   = (const float*)d_in[8];
    const float* dw_w = (const float*)d_in[9];
    const float* dw_b = (const float*)d_in[10];
    const float* ln_g = (const float*)d_in[11];
    const float* ln_b = (const float*)d_in[12];
    const float* pw_w = (const float*)d_in[13];
    const float* rpe  = (const float*)d_in[14];

    float *q, *xs, *k, *v, *ob;
    float2* pos;
    cudaGetSymbolAddress((void**)&q,   g_q);
    cudaGetSymbolAddress((void**)&xs,  g_xs);
    cudaGetSymbolAddress((void**)&k,   g_k);
    cudaGetSymbolAddress((void**)&v,   g_v);
    cudaGetSymbolAddress((void**)&ob,  g_o);
    cudaGetSymbolAddress((void**)&pos, g_pos);

    const int GSM = (2*64*AS_STRIDE + 2*32*BS_STRIDE) * 4;   // 53248 B
    cudaFuncSetAttribute(gemm_mma, cudaFuncAttributeMaxDynamicSharedMemorySize, GSM);
    cudaFuncSetAttribute(gemm_mma_kv, cudaFuncAttributeMaxDynamicSharedMemorySize, GSM);
    const int ASM = (10240 + 4608 + 512 + 128 + 32) * 4;     // 62080 B
    cudaFuncSetAttribute(attn_kernel, cudaFuncAttributeMaxDynamicSharedMemorySize, ASM);

    gemm_mma<<<dim3(8, 6, 2), 256, GSM>>>(Wq, bq, x, q);
    dwconv_kernel<<<768, 256>>>(q, dw_w, dw_b, k);
    offs_kernel<<<96, 256>>>(k, ln_g, ln_b, pw_w, pos);
    sample_kernel<<<3072, 256>>>(x, pos, xs);
    gemm_mma_kv<<<dim3(8, 12, 2), 256, GSM>>>(Wk, bk, Wv, bv, xs, k, v);
    attn_kernel<<<dim3(64, 24), 256, ASM>>>(q, k, v, pos, rpe, ob);
    gemm_mma<<<dim3(8, 6, 2), 256, GSM>>>(Wo, bo, ob, (float*)d_out);
}

// round 14
// speedup vs baseline: 1.1657x; 1.1657x over previous
#include <cuda_runtime.h>
#include <math.h>
#include <stdint.h>

// ---------------- scratch ----------------
#define NBUF (2*384*1024)
__device__ float g_q [NBUF];
__device__ float g_xs[NBUF];
__device__ float g_k [NBUF];
__device__ float g_v [NBUF];
__device__ float g_o [NBUF];
__device__ float2 g_pos[12*1024];

#define SCALE 0.17677669529663687f

typedef unsigned long long u64;
__device__ __forceinline__ uint32_t f2tf(float f) {
    uint32_t u; asm("cvt.rna.tf32.f32 %0, %1;" : "=r"(u) : "f"(f)); return u;
}
__device__ __forceinline__ void mma_tf32(float* d, const uint32_t* a, const uint32_t* b) {
    asm volatile("mma.sync.aligned.m16n8k8.row.col.f32.tf32.tf32.f32 "
        "{%0,%1,%2,%3}, {%4,%5,%6,%7}, {%8,%9}, {%0,%1,%2,%3};"
        : "+f"(d[0]), "+f"(d[1]), "+f"(d[2]), "+f"(d[3])
        : "r"(a[0]), "r"(a[1]), "r"(a[2]), "r"(a[3]), "r"(b[0]), "r"(b[1]));
}
// packed fp32x2 fma (sm_100+ PTX, base-arch feature)
__device__ __forceinline__ u64 pack2(float x) {
    u64 d; asm("mov.b64 %0, {%1, %1};" : "=l"(d) : "f"(x)); return d;
}
__device__ __forceinline__ void fma2(u64& d, u64 a, u64 b) {
    asm("fma.rn.f32x2 %0, %1, %2, %0;" : "+l"(d) : "l"(a), "l"(b));
}

// =======================================================================
// Channel-major tf32 mma GEMM (round 8, unchanged)
// =======================================================================
#define AS_STRIDE 36
#define BS_STRIDE 136
__device__ void gemm_body(
    const float* __restrict__ W, const float* __restrict__ bias,
    const float* __restrict__ X, float* __restrict__ Y,
    int m0, int n0)
{
    extern __shared__ float dsm[];
    float* Asm = dsm;                    // [2][64*36]
    float* Bsm = dsm + 2*64*AS_STRIDE;   // [2][32*136]

    int tid = threadIdx.x, lane = tid & 31, wid = tid >> 5;
    int wm = wid & 1, wn = wid >> 1;
    int g = lane >> 2, c = lane & 3;

    int ar = tid >> 2, aq = (tid & 3) * 8;
    int kb = tid >> 3, nq = (tid & 7) * 16;
    const float* Wp = W + (size_t)(m0 + ar) * 384 + aq;
    const float* Xp = X + (size_t)kb * 1024 + n0 + nq;

    float4 pa[2], pb[4];
    #pragma unroll
    for (int i = 0; i < 2; i++) pa[i] = *(const float4*)(Wp + i*4);
    #pragma unroll
    for (int i = 0; i < 4; i++) pb[i] = *(const float4*)(Xp + i*4);

    float acc[2][4][4];
    #pragma unroll
    for (int mt = 0; mt < 2; mt++)
        #pragma unroll
        for (int nt = 0; nt < 4; nt++)
            #pragma unroll
            for (int i = 0; i < 4; i++) acc[mt][nt][i] = 0.f;

    int buf = 0;
    #pragma unroll 1
    for (int ch = 0; ch < 12; ch++) {
        float* Asb = Asm + buf * 64 * AS_STRIDE;
        float* Bsb = Bsm + buf * 32 * BS_STRIDE;
        #pragma unroll
        for (int i = 0; i < 2; i++) {
            uint4 t = make_uint4(f2tf(pa[i].x), f2tf(pa[i].y), f2tf(pa[i].z), f2tf(pa[i].w));
            *(uint4*)&Asb[ar*AS_STRIDE + aq + i*4] = t;
        }
        #pragma unroll
        for (int i = 0; i < 4; i++) {
            uint4 t = make_uint4(f2tf(pb[i].x), f2tf(pb[i].y), f2tf(pb[i].z), f2tf(pb[i].w));
            *(uint4*)&Bsb[kb*BS_STRIDE + nq + i*4] = t;
        }
        __syncthreads();
        if (ch < 11) {
            #pragma unroll
            for (int i = 0; i < 2; i++) pa[i] = *(const float4*)(Wp + (ch+1)*32 + i*4);
            #pragma unroll
            for (int i = 0; i < 4; i++) pb[i] = *(const float4*)(Xp + (size_t)(ch+1)*32*1024 + i*4);
        }
        const uint32_t* Au = (const uint32_t*)Asb;
        const uint32_t* Bu = (const uint32_t*)Bsb;
        #pragma unroll
        for (int kk = 0; kk < 4; kk++) {
            uint32_t afr[2][4];
            #pragma unroll
            for (int mt = 0; mt < 2; mt++) {
                int rb = wm*32 + mt*16;
                afr[mt][0] = Au[(rb + g    )*AS_STRIDE + kk*8 + c];
                afr[mt][1] = Au[(rb + g + 8)*AS_STRIDE + kk*8 + c];
                afr[mt][2] = Au[(rb + g    )*AS_STRIDE + kk*8 + c + 4];
                afr[mt][3] = Au[(rb + g + 8)*AS_STRIDE + kk*8 + c + 4];
            }
            #pragma unroll
            for (int nt = 0; nt < 4; nt++) {
                int nb = wn*32 + nt*8;
                uint32_t bfr[2];
                bfr[0] = Bu[(kk*8 + c    )*BS_STRIDE + nb + g];
                bfr[1] = Bu[(kk*8 + c + 4)*BS_STRIDE + nb + g];
                mma_tf32(acc[0][nt], afr[0], bfr);
                mma_tf32(acc[1][nt], afr[1], bfr);
            }
        }
        buf ^= 1;
    }

    int c2 = (lane & 3) * 2;
    #pragma unroll
    for (int mt = 0; mt < 2; mt++) {
        int row = m0 + wm*32 + mt*16 + g;
        float b0 = bias[row], b1 = bias[row + 8];
        #pragma unroll
        for (int nt = 0; nt < 4; nt++) {
            int col = n0 + wn*32 + nt*8 + c2;
            *(float2*)&Y[(size_t)row*1024 + col] =
                make_float2(acc[mt][nt][0] + b0, acc[mt][nt][1] + b0);
            *(float2*)&Y[(size_t)(row + 8)*1024 + col] =
                make_float2(acc[mt][nt][2] + b1, acc[mt][nt][3] + b1);
        }
    }
}

__global__ __launch_bounds__(256) void gemm_mma(
    const float* __restrict__ W, const float* __restrict__ bias,
    const float* __restrict__ X, float* __restrict__ Y)
{
    int b = blockIdx.z;
    gemm_body(W, bias, X + (size_t)b*393216, Y + (size_t)b*393216,
              blockIdx.y*64, blockIdx.x*128);
}

__global__ __launch_bounds__(256) void gemm_mma_kv(
    const float* __restrict__ Wk, const float* __restrict__ bk,
    const float* __restrict__ Wv, const float* __restrict__ bv,
    const float* __restrict__ X, float* __restrict__ Yk, float* __restrict__ Yv)
{
    int b = blockIdx.z;
    int sel = blockIdx.y >= 6;
    int m0 = (blockIdx.y - sel*6) * 64;
    gemm_body(sel ? Wv : Wk, sel ? bv : bk, X + (size_t)b*393216,
              (sel ? Yv : Yk) + (size_t)b*393216, m0, blockIdx.x*128);
}

// =======================================================================
// depthwise 7x7 conv (round 2/8, unchanged)
// =======================================================================
__global__ __launch_bounds__(256) void dwconv_kernel(
    const float* __restrict__ q, const float* __restrict__ dw_w,
    const float* __restrict__ dw_b, float* __restrict__ tmp)
{
    int plane = blockIdx.x;
    int ch = plane & 63;
    __shared__ float s[1024];
    __shared__ float w[49];
    const float* qp = q + (size_t)plane * 1024;
    int tid = threadIdx.x;
    *(float4*)&s[tid*4] = *(const float4*)(qp + tid*4);
    if (tid < 49) w[tid] = dw_w[ch*49 + tid];
    float bch = dw_b[ch];
    __syncthreads();
    #pragma unroll
    for (int pp = 0; pp < 4; pp++) {
        int pix = tid + pp*256;
        int py = pix >> 5, px = pix & 31;
        float a = bch;
        #pragma unroll
        for (int ky = 0; ky < 7; ky++) {
            int iy = py + ky - 3;
            if (iy < 0 || iy > 31) continue;
            #pragma unroll
            for (int kx = 0; kx < 7; kx++) {
                int ix = px + kx - 3;
                if (ix < 0 || ix > 31) continue;
                a += w[ky*7+kx] * s[iy*32+ix];
            }
        }
        tmp[(size_t)plane*1024 + pix] = a;
    }
}

// =======================================================================
// LN + GELU + 1x1 + tanh -> pos (round 2/8, unchanged)
// =======================================================================
__global__ __launch_bounds__(256) void offs_kernel(
    const float* __restrict__ tmp, const float* __restrict__ ln_g,
    const float* __restrict__ ln_b, const float* __restrict__ pw_w,
    float2* __restrict__ pos)
{
    int bg = blockIdx.x >> 3;
    int p0 = (blockIdx.x & 7) * 128;
    int tid = threadIdx.x;
    int pl = tid & 127, half = tid >> 7;
    int pix = p0 + pl;
    const float* tp = tmp + (size_t)bg*65536 + (size_t)half*32768 + pix;

    __shared__ float red[256], red2[256], mu_s[128], rs_s[128];

    float vals[32];
    float s1 = 0.f;
    #pragma unroll
    for (int i = 0; i < 32; i++) { vals[i] = tp[i*1024]; s1 += vals[i]; }
    red[tid] = s1;
    __syncthreads();
    if (half == 0) mu_s[pl] = (red[pl] + red[pl+128]) * (1.f/64.f);
    __syncthreads();
    float mu = mu_s[pl];
    float s2 = 0.f;
    #pragma unroll
    for (int i = 0; i < 32; i++) { float d = vals[i]-mu; s2 += d*d; }
    red[tid] = s2;
    __syncthreads();
    if (half == 0) rs_s[pl] = rsqrtf((red[pl]+red[pl+128])*(1.f/64.f) + 1e-5f);
    __syncthreads();
    float rs = rs_s[pl];
    float sy = 0.f, sx = 0.f;
    #pragma unroll
    for (int i = 0; i < 32; i++) {
        int cch = half*32 + i;
        float o = (vals[i]-mu)*rs*ln_g[cch] + ln_b[cch];
        o = 0.5f*o*(1.f + erff(o*0.70710678118654752f));
        sy += o * pw_w[cch];
        sx += o * pw_w[64+cch];
    }
    red[tid] = sy; red2[tid] = sx;
    __syncthreads();
    if (half == 0) {
        float oy = tanhf(red[pl]+red[pl+128]) * 0.0625f;
        float ox = tanhf(red2[pl]+red2[pl+128]) * 0.0625f;
        int py = pix >> 5, px = pix & 31;
        float refy = ((py + 0.5f)*(1.f/16.f)) - 1.f;
        float refx = ((px + 0.5f)*(1.f/16.f)) - 1.f;
        pos[bg*1024 + pix] = make_float2(ox + refx, oy + refy);
    }
}

// =======================================================================
// grid sample (round 2/8, unchanged)
// =======================================================================
__global__ __launch_bounds__(256) void sample_kernel(
    const float* __restrict__ x, const float2* __restrict__ pos,
    float* __restrict__ xs)
{
    int idx = blockIdx.x * 256 + threadIdx.x;
    int s  = idx & 1023;
    int bg = idx >> 16;
    float2 p = pos[bg * 1024 + s];
    float gx = (p.x + 1.f) * 0.5f * 31.f;
    float gy = (p.y + 1.f) * 0.5f * 31.f;
    float x0f = floorf(gx), y0f = floorf(gy);
    float wx = gx - x0f, wy = gy - y0f;
    int x0 = (int)x0f, y0 = (int)y0f;
    const float* xp = x + (size_t)(idx >> 10) * 1024;
    float r = 0.f;
    bool vx0 = (x0 >= 0) & (x0 <= 31), vx1 = (x0 >= -1) & (x0 <= 30);
    bool vy0 = (y0 >= 0) & (y0 <= 31), vy1 = (y0 >= -1) & (y0 <= 30);
    if (vx0 && vy0) r += (1.f - wx) * (1.f - wy) * xp[y0 * 32 + x0];
    if (vx1 && vy0) r += wx * (1.f - wy) * xp[y0 * 32 + x0 + 1];
    if (vx0 && vy1) r += (1.f - wx) * wy * xp[(y0 + 1) * 32 + x0];
    if (vx1 && vy1) r += wx * wy * xp[(y0 + 1) * 32 + x0 + 1];
    xs[idx] = r;
}

// =======================================================================
// fused attention (round-10 base; PV remapped: warp = n-split ->
// conflict-free p_s/v_s reads; cross-warp reduce via smem aliased on p_s)
// smem floats: p[1024*20] | v[128*36] | q[512] | redw[128] | fin[32]
// =======================================================================
#define P_STRIDE 20
#define V_STRIDE 36
#define ACC(r, j) (((float*)accp)[(((r) >> 1)*4 + (j))*2 + ((r) & 1)])
__global__ __launch_bounds__(256, 2) void attn_kernel(
    const float* __restrict__ qg, const float* __restrict__ kg,
    const float* __restrict__ vg, const float2* __restrict__ pos,
    const float* __restrict__ rpe, float* __restrict__ out)
{
    extern __shared__ float sm[];
    float* p_s  = sm;                       // 20480
    float* v_s  = sm + 20480;               // 4608
    float* q_s  = sm + 20480 + 4608;        // 512  [c*16 + r]
    float* redw = q_s + 512;                // 128  [r*8 + warp]
    float* fin  = redw + 128;               // 32

    int bh = blockIdx.y;
    int m0 = blockIdx.x * 16;
    int head = bh % 12;
    int bg = (bh / 12) * 6 + (head >> 1);
    int tid = threadIdx.x;
    int lane = tid & 31, warp = tid >> 5;

    #pragma unroll
    for (int i = tid; i < 512; i += 256) {
        int c = i >> 4, r = i & 15;
        q_s[i] = qg[(size_t)(bh*32 + c)*1024 + m0 + r] * SCALE;
    }
    __syncthreads();

    // ---- scores (f32x2: rows paired, k broadcast packed)
    u64 accp[8][4];
    #pragma unroll
    for (int p = 0; p < 8; p++)
        #pragma unroll
        for (int j = 0; j < 4; j++) accp[p][j] = 0ull;

    const float* kb = kg + (size_t)bh * 32768;
    #pragma unroll 4
    for (int c = 0; c < 32; c++) {
        u64 K0 = pack2(kb[c*1024 + tid]);
        u64 K1 = pack2(kb[c*1024 + tid + 256]);
        u64 K2 = pack2(kb[c*1024 + tid + 512]);
        u64 K3 = pack2(kb[c*1024 + tid + 768]);
        #pragma unroll
        for (int p = 0; p < 8; p++) {
            u64 qp = *(const u64*)&q_s[c*16 + p*2];
            fma2(accp[p][0], qp, K0);
            fma2(accp[p][1], qp, K1);
            fma2(accp[p][2], qp, K2);
            fma2(accp[p][3], qp, K3);
        }
    }

    { // RPE bilinear bias (y constant over the 16 rows of this block)
        const float* T = rpe + head * 3969;
        int yq = m0 >> 5, xb = m0 & 31;
        float qy  = (yq + 0.5f) * (1.f/16.f) - 1.f;
        float qx0 = (xb + 0.5f) * (1.f/16.f) - 1.f;
        #pragma unroll
        for (int j = 0; j < 4; j++) {
            float2 p = pos[bg*1024 + tid + 256*j];
            float gy = fmaf(qy - p.y, 15.5f, 31.f);
            float y0f = floorf(gy);
            float wy = gy - y0f;
            int y0 = (int)y0f;
            float vy0 = (y0 >= 0 && y0 <= 62) ? 1.f : 0.f;
            float vy1 = (y0 >= -1 && y0 <= 61) ? 1.f : 0.f;
            int yc0 = min(max(y0, 0), 62);
            int yc1 = min(max(y0 + 1, 0), 62);
            const float* T0 = T + yc0*63;
            const float* T1 = T + yc1*63;
            float w0y = (1.f - wy) * vy0;
            float w1y = wy * vy1;
            float Cx = fmaf(qx0 - p.x, 15.5f, 31.f);
            #pragma unroll
            for (int r = 0; r < 16; r++) {
                float gx = fmaf((float)r, 0.96875f, Cx);
                float x0f = floorf(gx);
                float wx = gx - x0f;
                int x0 = (int)x0f;
                float vx0 = (x0 >= 0 && x0 <= 62) ? 1.f : 0.f;
                float vx1 = (x0 >= -1 && x0 <= 61) ? 1.f : 0.f;
                int xc0 = min(max(x0, 0), 62);
                int xc1 = min(max(x0 + 1, 0), 62);
                float t00 = T0[xc0], t01 = T0[xc1];
                float t10 = T1[xc0], t11 = T1[xc1];
                float wx0 = (1.f - wx) * vx0, wx1 = wx * vx1;
                ACC(r, j) += w0y * (wx0*t00 + wx1*t01) + w1y * (wx0*t10 + wx1*t11);
            }
        }
    }

    // softmax
    float rv[16];
    #pragma unroll
    for (int r = 0; r < 16; r++)
        rv[r] = fmaxf(fmaxf(ACC(r,0), ACC(r,1)), fmaxf(ACC(r,2), ACC(r,3)));
    #pragma unroll
    for (int off = 16; off >= 1; off >>= 1)
        #pragma unroll
        for (int r = 0; r < 16; r++)
            rv[r] = fmaxf(rv[r], __shfl_xor_sync(0xffffffffu, rv[r], off));
    if (lane == 0)
        #pragma unroll
        for (int r = 0; r < 16; r++) redw[r*8 + warp] = rv[r];
    __syncthreads();
    if (tid < 16) {
        float m = redw[tid*8];
        #pragma unroll
        for (int w = 1; w < 8; w++) m = fmaxf(m, redw[tid*8 + w]);
        fin[tid] = m;
    }
    __syncthreads();
    #pragma unroll
    for (int r = 0; r < 16; r++) {
        float m = fin[r];
        float s = 0.f;
        #pragma unroll
        for (int j = 0; j < 4; j++) { ACC(r,j) = __expf(ACC(r,j) - m); s += ACC(r,j); }
        rv[r] = s;
    }
    #pragma unroll
    for (int off = 16; off >= 1; off >>= 1)
        #pragma unroll
        for (int r = 0; r < 16; r++)
            rv[r] += __shfl_xor_sync(0xffffffffu, rv[r], off);
    if (lane == 0)
        #pragma unroll
        for (int r = 0; r < 16; r++) redw[r*8 + warp] = rv[r];
    __syncthreads();
    if (tid < 16) {
        float s = 0.f;
        #pragma unroll
        for (int w = 0; w < 8; w++) s += redw[tid*8 + w];
        fin[16 + tid] = 1.f / s;
    }

    // store exp'd p transposed: p_s[n][r], stride 20
    #pragma unroll
    for (int j = 0; j < 4; j++) {
        int n = tid + 256*j;
        #pragma unroll
        for (int rq = 0; rq < 4; rq++)
            *(float4*)&p_s[n*P_STRIDE + rq*4] =
                make_float4(ACC(rq*4+0, j), ACC(rq*4+1, j), ACC(rq*4+2, j), ACC(rq*4+3, j));
    }
    __syncthreads();

    // ---- PV: warp = n-split (nl = i*8 + warp); lane: cq = (lane&7)*4, rq = (lane>>3)*4
    // p_s read: 4 broadcast segments; v_s read: 32 consecutive floats -> conflict-free.
    int cq = (lane & 7) * 4;
    int rq = (lane >> 3) * 4;
    u64 o2[4][2];                   // [ri][ci-pair]
    #pragma unroll
    for (int ri = 0; ri < 4; ri++) { o2[ri][0] = 0ull; o2[ri][1] = 0ull; }
    const float* vb = vg + (size_t)bh * 32768;

    int lc = tid & 31;
    int nb = (tid >> 5) * 16;
    #pragma unroll 1
    for (int chk = 0; chk < 8; chk++) {
        #pragma unroll
        for (int ii = 0; ii < 16; ii += 4) {
            float4 t = *(const float4*)(vb + lc*1024 + chk*128 + nb + ii);
            v_s[(nb+ii+0)*V_STRIDE + lc] = t.x;
            v_s[(nb+ii+1)*V_STRIDE + lc] = t.y;
            v_s[(nb+ii+2)*V_STRIDE + lc] = t.z;
            v_s[(nb+ii+3)*V_STRIDE + lc] = t.w;
        }
        __syncthreads();
        #pragma unroll
        for (int i = 0; i < 16; i++) {
            int nl = i*8 + warp;
            float4 p4 = *(const float4*)&p_s[(chk*128 + nl)*P_STRIDE + rq];
            ulonglong2 vv = *(const ulonglong2*)&v_s[nl*V_STRIDE + cq];
            u64 P0 = pack2(p4.x), P1 = pack2(p4.y), P2 = pack2(p4.z), P3 = pack2(p4.w);
            fma2(o2[0][0], P0, vv.x); fma2(o2[0][1], P0, vv.y);
            fma2(o2[1][0], P1, vv.x); fma2(o2[1][1], P1, vv.y);
            fma2(o2[2][0], P2, vv.x); fma2(o2[2][1], P2, vv.y);
            fma2(o2[3][0], P3, vv.x); fma2(o2[3][1], P3, vv.y);
        }
        __syncthreads();
    }

    // ---- cross-warp reduce: dpart[8][16][36] aliased on p_s (all p reads done)
    float* dpart = sm;
    #pragma unroll
    for (int ri = 0; ri < 4; ri++) {
        float2 a = *(float2*)&o2[ri][0];
        float2 b = *(float2*)&o2[ri][1];
        *(float4*)&dpart[warp*576 + (rq + ri)*V_STRIDE + cq] =
            make_float4(a.x, a.y, b.x, b.y);
    }
    __syncthreads();
    {
        int col = tid >> 3;             // 0..31 channel
        int r0 = (tid & 7) * 2;         // even row
        float s0 = 0.f, s1 = 0.f;
        #pragma unroll
        for (int w = 0; w < 8; w++) {
            s0 += dpart[w*576 + r0*V_STRIDE + col];
            s1 += dpart[w*576 + (r0+1)*V_STRIDE + col];
        }
        float2 o = make_float2(s0 * fin[16 + r0], s1 * fin[16 + r0 + 1]);
        *(float2*)&out[(size_t)(bh*32 + col)*1024 + m0 + r0] = o;
    }
}

// ---------------- launch ----------------
extern "C" void kernel_launch(void* const* d_in, const int* in_sizes, int n_in,
                              void* d_out, int out_size)
{
    const float* x    = (const float*)d_in[0];
    const float* Wq   = (const float*)d_in[1];
    const float* bq   = (const float*)d_in[2];
    const float* Wk   = (const float*)d_in[3];
    const float* bk   = (const float*)d_in[4];
    const float* Wv   = (const float*)d_in[5];
    const float* bv   = (const float*)d_in[6];
    const float* Wo   = (const float*)d_in[7];
    const float* bo   = (const float*)d_in[8];
    const float* dw_w = (const float*)d_in[9];
    const float* dw_b = (const float*)d_in[10];
    const float* ln_g = (const float*)d_in[11];
    const float* ln_b = (const float*)d_in[12];
    const float* pw_w = (const float*)d_in[13];
    const float* rpe  = (const float*)d_in[14];

    float *q, *xs, *k, *v, *ob;
    float2* pos;
    cudaGetSymbolAddress((void**)&q,   g_q);
    cudaGetSymbolAddress((void**)&xs,  g_xs);
    cudaGetSymbolAddress((void**)&k,   g_k);
    cudaGetSymbolAddress((void**)&v,   g_v);
    cudaGetSymbolAddress((void**)&ob,  g_o);
    cudaGetSymbolAddress((void**)&pos, g_pos);

    const int GSM = (2*64*AS_STRIDE + 2*32*BS_STRIDE) * 4;   // 53248 B
    cudaFuncSetAttribute(gemm_mma, cudaFuncAttributeMaxDynamicSharedMemorySize, GSM);
    cudaFuncSetAttribute(gemm_mma_kv, cudaFuncAttributeMaxDynamicSharedMemorySize, GSM);
    const int ASM = (20480 + 4608 + 512 + 128 + 32) * 4;     // 103040 B
    cudaFuncSetAttribute(attn_kernel, cudaFuncAttributeMaxDynamicSharedMemorySize, ASM);

    gemm_mma<<<dim3(8, 6, 2), 256, GSM>>>(Wq, bq, x, q);
    dwconv_kernel<<<768, 256>>>(q, dw_w, dw_b, k);
    offs_kernel<<<96, 256>>>(k, ln_g, ln_b, pw_w, pos);
    sample_kernel<<<3072, 256>>>(x, pos, xs);
    gemm_mma_kv<<<dim3(8, 12, 2), 256, GSM>>>(Wk, bk, Wv, bv, xs, k, v);
    attn_kernel<<<dim3(64, 24), 256, ASM>>>(q, k, v, pos, rpe, ob);
    gemm_mma<<<dim3(8, 6, 2), 256, GSM>>>(Wo, bo, ob, (float*)d_out);
}